// round 5
// baseline (speedup 1.0000x reference)
#include <cuda_runtime.h>

// Problem shapes (fixed by setup_inputs): N=50000, E=1600000, F_in=128, H=4, C=32
#define MAXN 50000
#define MAXE 1600000
#define MAXET (MAXE + MAXN)

// ---- static device scratch (no allocations allowed) ----
__device__ float g_xp1[MAXN * 128];     // layer1 projection  [N,H*C]
__device__ float g_h1 [MAXN * 128];     // elu(gat1) output   [N,128]
__device__ float g_xp2[MAXN * 32];      // layer2 projection  [N,32]
__device__ float g_als1[MAXN * 4];
__device__ float g_ald1[MAXN * 4];
__device__ float g_als2[MAXN];
__device__ float g_ald2[MAXN];
__device__ float g_ex  [(size_t)MAXET * 4];  // per-edge exp numerators
__device__ int   g_srcs[MAXET];              // CSR: src sorted by dst
__device__ int   g_deg [MAXN];
__device__ int   g_off [MAXN + 1];
__device__ int   g_cur [MAXN];
__device__ int   g_is64;                      // 1 if edge_index buffer is int64

// ---------------- edge dtype detection ----------------
// int64 values < 2^31 interpreted as int32 pairs -> odd positions all zero.
__global__ void k_detect(const int* __restrict__ ei32) {
    __shared__ int nz;
    if (threadIdx.x == 0) nz = 0;
    __syncthreads();
    int acc = 0;
    for (int k = threadIdx.x; k < 2048; k += blockDim.x)
        acc |= ei32[2 * k + 1];
    if (acc) atomicOr(&nz, 1);
    __syncthreads();
    if (threadIdx.x == 0) g_is64 = (nz == 0) ? 1 : 0;
}

__device__ __forceinline__ int load_edge(const void* ei, int is64, size_t idx) {
    if (is64) return (int)((const long long*)ei)[idx];
    return ((const int*)ei)[idx];
}

// ---------------- CSR construction ----------------

__global__ void k_zero_deg(int N) {
    int i = blockIdx.x * blockDim.x + threadIdx.x;
    if (i < N) g_deg[i] = 0;
}

__global__ void k_count(const void* __restrict__ ei, int N, int E) {
    int is64 = g_is64;
    int total = E + N;
    for (int i = blockIdx.x * blockDim.x + threadIdx.x; i < total;
         i += gridDim.x * blockDim.x) {
        int d = (i < E) ? load_edge(ei, is64, (size_t)E + i) : (i - E);  // self-loop tail
        if ((unsigned)d >= (unsigned)N) d = 0;  // defensive clamp
        atomicAdd(&g_deg[d], 1);
    }
}

// single-block exclusive scan over N<=50176 degrees
__global__ void k_scan(int N) {
    __shared__ int sums[1024];
    int t = threadIdx.x;
    int per = (N + 1023) / 1024;
    int s0 = t * per;
    int s1 = s0 + per; if (s1 > N) s1 = N;
    int s = 0;
    for (int i = s0; i < s1; ++i) s += g_deg[i];
    sums[t] = s;
    __syncthreads();
    for (int d = 1; d < 1024; d <<= 1) {
        int v = (t >= d) ? sums[t - d] : 0;
        __syncthreads();
        sums[t] += v;
        __syncthreads();
    }
    int run = sums[t] - s;  // exclusive prefix of this thread's range
    for (int i = s0; i < s1; ++i) {
        g_off[i] = run;
        g_cur[i] = run;
        run += g_deg[i];
    }
    if (t == 1023) g_off[N] = sums[1023];
}

__global__ void k_scatter(const void* __restrict__ ei, int N, int E) {
    int is64 = g_is64;
    int total = E + N;
    for (int i = blockIdx.x * blockDim.x + threadIdx.x; i < total;
         i += gridDim.x * blockDim.x) {
        int s, d;
        if (i < E) {
            s = load_edge(ei, is64, (size_t)i);
            d = load_edge(ei, is64, (size_t)E + i);
        } else {
            s = d = i - E;
        }
        if ((unsigned)s >= (unsigned)N) s = 0;
        if ((unsigned)d >= (unsigned)N) d = 0;
        int p = atomicAdd(&g_cur[d], 1);
        g_srcs[p] = s;
    }
}

// ---------------- layer 1: projection GEMM  xp1 = x @ W1 ----------------
// 256 threads, 32 rows x 128 cols per block, K tiled by 32.
__global__ void k_gemm1(const float* __restrict__ x, const float* __restrict__ W, int N) {
    __shared__ float xs[32][33];
    __shared__ float ws[32][128];
    int tid = threadIdx.x;
    int tx = tid & 31, ty = tid >> 5;
    int row0 = blockIdx.x * 32;
    float acc[4][4] = {};
    for (int k0 = 0; k0 < 128; k0 += 32) {
        #pragma unroll
        for (int i = 0; i < 16; ++i) {
            int idx = tid + i * 256;
            int kk = idx >> 7, cc = idx & 127;
            ws[kk][cc] = W[(size_t)(k0 + kk) * 128 + cc];
        }
        #pragma unroll
        for (int i = 0; i < 4; ++i) {
            int idx = tid + i * 256;
            int rr = idx >> 5, kk = idx & 31;
            int r = row0 + rr;
            xs[rr][kk] = (r < N) ? x[(size_t)r * 128 + k0 + kk] : 0.f;
        }
        __syncthreads();
        #pragma unroll
        for (int kk = 0; kk < 32; ++kk) {
            float a[4], b[4];
            #pragma unroll
            for (int i = 0; i < 4; ++i) a[i] = xs[ty * 4 + i][kk];
            #pragma unroll
            for (int j = 0; j < 4; ++j) b[j] = ws[kk][tx + j * 32];
            #pragma unroll
            for (int i = 0; i < 4; ++i)
                #pragma unroll
                for (int j = 0; j < 4; ++j) acc[i][j] += a[i] * b[j];
        }
        __syncthreads();
    }
    #pragma unroll
    for (int i = 0; i < 4; ++i) {
        int r = row0 + ty * 4 + i;
        if (r < N) {
            #pragma unroll
            for (int j = 0; j < 4; ++j)
                g_xp1[(size_t)r * 128 + tx + j * 32] = acc[i][j];
        }
    }
}

// per-node attention logits: als1[n,h] = sum_c xp1[n,h,c]*a_src[h,c]  (warp/node)
__global__ void k_logits1(const float* __restrict__ a_src, const float* __restrict__ a_dst, int N) {
    int w = (blockIdx.x * blockDim.x + threadIdx.x) >> 5;
    int lane = threadIdx.x & 31;
    if (w >= N) return;
    #pragma unroll
    for (int h = 0; h < 4; ++h) {
        float v = g_xp1[(size_t)w * 128 + h * 32 + lane];
        float s = v * a_src[h * 32 + lane];
        float d = v * a_dst[h * 32 + lane];
        #pragma unroll
        for (int o = 16; o; o >>= 1) {
            s += __shfl_xor_sync(0xffffffffu, s, o);
            d += __shfl_xor_sync(0xffffffffu, d, o);
        }
        if (lane == 0) { g_als1[w * 4 + h] = s; g_ald1[w * 4 + h] = d; }
    }
}

// layer-1 segment softmax + aggregation. One warp per destination node.
__global__ void k_agg1(const float* __restrict__ b1, int N) {
    int w = (blockIdx.x * blockDim.x + threadIdx.x) >> 5;
    int lane = threadIdx.x & 31;
    if (w >= N) return;
    int beg = g_off[w], end = g_off[w + 1];
    float ald0 = g_ald1[w * 4 + 0], ald1v = g_ald1[w * 4 + 1];
    float ald2 = g_ald1[w * 4 + 2], ald3 = g_ald1[w * 4 + 3];
    float den0 = 0.f, den1 = 0.f, den2 = 0.f, den3 = 0.f;
    // pass 1: lane-parallel exp numerators + denominator
    for (int e = beg + lane; e < end; e += 32) {
        int s = g_srcs[e];
        float4 al = *(const float4*)(g_als1 + (size_t)s * 4);
        float t0 = al.x + ald0;  t0 = t0 > 0.f ? t0 : 0.2f * t0;
        float t1 = al.y + ald1v; t1 = t1 > 0.f ? t1 : 0.2f * t1;
        float t2 = al.z + ald2;  t2 = t2 > 0.f ? t2 : 0.2f * t2;
        float t3 = al.w + ald3;  t3 = t3 > 0.f ? t3 : 0.2f * t3;
        float4 ex;
        ex.x = __expf(t0); ex.y = __expf(t1); ex.z = __expf(t2); ex.w = __expf(t3);
        *(float4*)(g_ex + (size_t)e * 4) = ex;
        den0 += ex.x; den1 += ex.y; den2 += ex.z; den3 += ex.w;
    }
    __syncwarp();
    #pragma unroll
    for (int o = 16; o; o >>= 1) {
        den0 += __shfl_xor_sync(0xffffffffu, den0, o);
        den1 += __shfl_xor_sync(0xffffffffu, den1, o);
        den2 += __shfl_xor_sync(0xffffffffu, den2, o);
        den3 += __shfl_xor_sync(0xffffffffu, den3, o);
    }
    float inv0 = 1.f / (den0 + 1e-16f), inv1 = 1.f / (den1 + 1e-16f);
    float inv2 = 1.f / (den2 + 1e-16f), inv3 = 1.f / (den3 + 1e-16f);
    // pass 2: coalesced gather-accumulate (lane = channel c)
    float a0 = 0.f, a1 = 0.f, a2 = 0.f, a3 = 0.f;
    for (int e = beg; e < end; ++e) {
        int s = g_srcs[e];                                  // broadcast
        float4 ex = *(const float4*)(g_ex + (size_t)e * 4); // broadcast
        const float* xr = g_xp1 + (size_t)s * 128;
        a0 += xr[lane]      * (ex.x * inv0);
        a1 += xr[32 + lane] * (ex.y * inv1);
        a2 += xr[64 + lane] * (ex.z * inv2);
        a3 += xr[96 + lane] * (ex.w * inv3);
    }
    float v;
    v = a0 + b1[lane];      g_h1[(size_t)w * 128 + lane]      = v > 0.f ? v : (__expf(v) - 1.f);
    v = a1 + b1[32 + lane]; g_h1[(size_t)w * 128 + 32 + lane] = v > 0.f ? v : (__expf(v) - 1.f);
    v = a2 + b1[64 + lane]; g_h1[(size_t)w * 128 + 64 + lane] = v > 0.f ? v : (__expf(v) - 1.f);
    v = a3 + b1[96 + lane]; g_h1[(size_t)w * 128 + 96 + lane] = v > 0.f ? v : (__expf(v) - 1.f);
}

// layer 2 projection xp2 = h1 @ W2 (128->32), fused logits. 8 nodes/block, warp/node.
__global__ void k_gemm2(const float* __restrict__ W2, const float* __restrict__ a_src2,
                        const float* __restrict__ a_dst2, int N) {
    __shared__ float ws[128 * 32];
    __shared__ float hs[8][128];
    int tid = threadIdx.x, lane = tid & 31, w = tid >> 5;
    int n = blockIdx.x * 8 + w;
    for (int i = tid; i < 4096; i += 256) ws[i] = W2[i];
    if (n < N)
        for (int k = lane; k < 128; k += 32) hs[w][k] = g_h1[(size_t)n * 128 + k];
    __syncthreads();
    if (n >= N) return;
    float acc = 0.f;
    #pragma unroll
    for (int k4 = 0; k4 < 32; ++k4) {
        float4 h4 = *(const float4*)&hs[w][k4 * 4];
        acc += h4.x * ws[(k4 * 4 + 0) * 32 + lane];
        acc += h4.y * ws[(k4 * 4 + 1) * 32 + lane];
        acc += h4.z * ws[(k4 * 4 + 2) * 32 + lane];
        acc += h4.w * ws[(k4 * 4 + 3) * 32 + lane];
    }
    g_xp2[(size_t)n * 32 + lane] = acc;
    float s = acc * a_src2[lane];
    float d = acc * a_dst2[lane];
    #pragma unroll
    for (int o = 16; o; o >>= 1) {
        s += __shfl_xor_sync(0xffffffffu, s, o);
        d += __shfl_xor_sync(0xffffffffu, d, o);
    }
    if (lane == 0) { g_als2[n] = s; g_ald2[n] = d; }
}

// layer-2 aggregation (H=1, C=32), warp per node, writes final output.
__global__ void k_agg2(const float* __restrict__ b2, float* __restrict__ out, int N) {
    int w = (blockIdx.x * blockDim.x + threadIdx.x) >> 5;
    int lane = threadIdx.x & 31;
    if (w >= N) return;
    int beg = g_off[w], end = g_off[w + 1];
    float ald = g_ald2[w];
    float den = 0.f;
    for (int e = beg + lane; e < end; e += 32) {
        int s = g_srcs[e];
        float t = g_als2[s] + ald;
        t = t > 0.f ? t : 0.2f * t;
        float ex = __expf(t);
        g_ex[e] = ex;
        den += ex;
    }
    __syncwarp();
    #pragma unroll
    for (int o = 16; o; o >>= 1) den += __shfl_xor_sync(0xffffffffu, den, o);
    float inv = 1.f / (den + 1e-16f);
    float acc = 0.f;
    for (int e = beg; e < end; ++e) {
        int s = g_srcs[e];
        acc += g_xp2[(size_t)s * 32 + lane] * (g_ex[e] * inv);
    }
    out[(size_t)w * 32 + lane] = acc + b2[lane];
}

extern "C" void kernel_launch(void* const* d_in, const int* in_sizes, int n_in,
                              void* d_out, int out_size) {
    const float* x      = (const float*)d_in[0];
    const void*  ei     = d_in[1];                 // int32 or int64, detected on device
    const float* W1     = (const float*)d_in[2];
    const float* a_src1 = (const float*)d_in[3];
    const float* a_dst1 = (const float*)d_in[4];
    const float* b1     = (const float*)d_in[5];
    const float* W2     = (const float*)d_in[6];
    const float* a_src2 = (const float*)d_in[7];
    const float* a_dst2 = (const float*)d_in[8];
    const float* b2     = (const float*)d_in[9];
    float* out = (float*)d_out;

    int N = in_sizes[0] / 128;  // 50000
    int E = in_sizes[1] / 2;    // 1600000

    // CSR build (per launch — no caching allowed)
    k_detect  <<<1, 256>>>((const int*)ei);
    k_zero_deg<<<(N + 255) / 256, 256>>>(N);
    k_count   <<<2048, 256>>>(ei, N, E);
    k_scan    <<<1, 1024>>>(N);
    k_scatter <<<2048, 256>>>(ei, N, E);

    // layer 1
    k_gemm1  <<<(N + 31) / 32, 256>>>(x, W1, N);
    k_logits1<<<(N + 7) / 8, 256>>>(a_src1, a_dst1, N);
    k_agg1   <<<(N + 7) / 8, 256>>>(b1, N);

    // layer 2
    k_gemm2<<<(N + 7) / 8, 256>>>(W2, a_src2, a_dst2, N);
    k_agg2 <<<(N + 7) / 8, 256>>>(b2, out, N);
}

// round 6
// speedup vs baseline: 1.3016x; 1.3016x over previous
#include <cuda_runtime.h>

// Problem shapes (fixed by setup_inputs): N=50000, E=1600000, F_in=128, H=4, C=32
#define MAXN 50000
#define MAXE 1600000
#define MAXET (MAXE + MAXN)
#define NBLK ((MAXN + 255) / 256)   // 196 scan blocks

// ---- static device scratch (no allocations allowed) ----
__device__ float g_xp1[MAXN * 128];     // layer1 projection  [N,H*C]
__device__ float g_h1 [MAXN * 128];     // elu(gat1) output   [N,128]
__device__ float g_xp2[MAXN * 32];      // layer2 projection  [N,32]
__device__ float g_als1[MAXN * 4];
__device__ float g_ald1[MAXN * 4];
__device__ float g_als2[MAXN];
__device__ float g_ald2[MAXN];
__device__ float g_ex  [(size_t)MAXET * 4];  // per-edge exp numerators
__device__ int   g_srcs[MAXET];              // CSR: src sorted by dst
__device__ int   g_deg [MAXN];
__device__ int   g_off [MAXN + 1];
__device__ int   g_cur [MAXN];
__device__ int   g_bsum[NBLK];
__device__ int   g_bpre[NBLK];
__device__ int   g_is64;                      // 1 if edge_index buffer is int64

// ---------------- edge dtype detection ----------------
// int64 values < 2^31 interpreted as int32 pairs -> odd positions all zero.
__global__ void k_detect(const int* __restrict__ ei32) {
    __shared__ int nz;
    if (threadIdx.x == 0) nz = 0;
    __syncthreads();
    int acc = 0;
    for (int k = threadIdx.x; k < 2048; k += blockDim.x)
        acc |= ei32[2 * k + 1];
    if (acc) atomicOr(&nz, 1);
    __syncthreads();
    if (threadIdx.x == 0) g_is64 = (nz == 0) ? 1 : 0;
}

__device__ __forceinline__ int load_edge(const void* ei, int is64, size_t idx) {
    if (is64) return (int)((const long long*)ei)[idx];
    return ((const int*)ei)[idx];
}

// ---------------- CSR construction ----------------

__global__ void k_zero_deg(int N) {
    int i = blockIdx.x * blockDim.x + threadIdx.x;
    if (i < N) g_deg[i] = 0;
}

__global__ void k_count(const void* __restrict__ ei, int N, int E) {
    int is64 = g_is64;
    int total = E + N;
    for (int i = blockIdx.x * blockDim.x + threadIdx.x; i < total;
         i += gridDim.x * blockDim.x) {
        int d = (i < E) ? load_edge(ei, is64, (size_t)E + i) : (i - E);  // self-loop tail
        if ((unsigned)d >= (unsigned)N) d = 0;  // defensive clamp
        atomicAdd(&g_deg[d], 1);
    }
}

// ---- parallel 3-phase exclusive scan over g_deg[0..N) ----

// phase 1: per-block exclusive scan (256 elems/block), block totals to g_bsum
__global__ void k_scan1(int N) {
    int i = blockIdx.x * 256 + threadIdx.x;
    int lane = threadIdx.x & 31, wid = threadIdx.x >> 5;
    int v = (i < N) ? g_deg[i] : 0;
    int x = v;
    #pragma unroll
    for (int o = 1; o < 32; o <<= 1) {
        int y = __shfl_up_sync(0xffffffffu, x, o);
        if (lane >= o) x += y;
    }
    __shared__ int ws[8];
    if (lane == 31) ws[wid] = x;
    __syncthreads();
    if (wid == 0) {
        int s = (lane < 8) ? ws[lane] : 0;
        #pragma unroll
        for (int o = 1; o < 8; o <<= 1) {
            int y = __shfl_up_sync(0xffffffffu, s, o);
            if (lane >= o) s += y;
        }
        if (lane < 8) ws[lane] = s;
    }
    __syncthreads();
    int warpoff = wid ? ws[wid - 1] : 0;
    if (i < N) g_off[i] = warpoff + x - v;   // block-local exclusive prefix
    if (threadIdx.x == 255) g_bsum[blockIdx.x] = ws[7];
}

// phase 2: single block scans the NBLK block sums; also writes g_off[N]
__global__ void k_scan2(int NB, int N) {
    __shared__ int sh[256];
    int t = threadIdx.x;
    int v = (t < NB) ? g_bsum[t] : 0;
    sh[t] = v;
    __syncthreads();
    for (int o = 1; o < 256; o <<= 1) {
        int y = (t >= o) ? sh[t - o] : 0;
        __syncthreads();
        sh[t] += y;
        __syncthreads();
    }
    if (t < NB) g_bpre[t] = sh[t] - v;  // exclusive
    if (t == 255) g_off[N] = sh[255];   // grand total = E + N
}

// phase 3: add block prefixes, init g_cur
__global__ void k_scan3(int N) {
    int i = blockIdx.x * 256 + threadIdx.x;
    if (i < N) {
        int o = g_off[i] + g_bpre[blockIdx.x];
        g_off[i] = o;
        g_cur[i] = o;
    }
}

__global__ void k_scatter(const void* __restrict__ ei, int N, int E) {
    int is64 = g_is64;
    int total = E + N;
    for (int i = blockIdx.x * blockDim.x + threadIdx.x; i < total;
         i += gridDim.x * blockDim.x) {
        int s, d;
        if (i < E) {
            s = load_edge(ei, is64, (size_t)i);
            d = load_edge(ei, is64, (size_t)E + i);
        } else {
            s = d = i - E;
        }
        if ((unsigned)s >= (unsigned)N) s = 0;
        if ((unsigned)d >= (unsigned)N) d = 0;
        int p = atomicAdd(&g_cur[d], 1);
        g_srcs[p] = s;
    }
}

// ---------------- layer 1: projection GEMM  xp1 = x @ W1 ----------------
// 256 threads, 32 rows x 128 cols per block, K tiled by 32.
__global__ void k_gemm1(const float* __restrict__ x, const float* __restrict__ W, int N) {
    __shared__ float xs[32][33];
    __shared__ float ws[32][128];
    int tid = threadIdx.x;
    int tx = tid & 31, ty = tid >> 5;
    int row0 = blockIdx.x * 32;
    float acc[4][4] = {};
    for (int k0 = 0; k0 < 128; k0 += 32) {
        #pragma unroll
        for (int i = 0; i < 16; ++i) {
            int idx = tid + i * 256;
            int kk = idx >> 7, cc = idx & 127;
            ws[kk][cc] = W[(size_t)(k0 + kk) * 128 + cc];
        }
        #pragma unroll
        for (int i = 0; i < 4; ++i) {
            int idx = tid + i * 256;
            int rr = idx >> 5, kk = idx & 31;
            int r = row0 + rr;
            xs[rr][kk] = (r < N) ? x[(size_t)r * 128 + k0 + kk] : 0.f;
        }
        __syncthreads();
        #pragma unroll
        for (int kk = 0; kk < 32; ++kk) {
            float a[4], b[4];
            #pragma unroll
            for (int i = 0; i < 4; ++i) a[i] = xs[ty * 4 + i][kk];
            #pragma unroll
            for (int j = 0; j < 4; ++j) b[j] = ws[kk][tx + j * 32];
            #pragma unroll
            for (int i = 0; i < 4; ++i)
                #pragma unroll
                for (int j = 0; j < 4; ++j) acc[i][j] += a[i] * b[j];
        }
        __syncthreads();
    }
    #pragma unroll
    for (int i = 0; i < 4; ++i) {
        int r = row0 + ty * 4 + i;
        if (r < N) {
            #pragma unroll
            for (int j = 0; j < 4; ++j)
                g_xp1[(size_t)r * 128 + tx + j * 32] = acc[i][j];
        }
    }
}

// per-node attention logits: als1[n,h] = sum_c xp1[n,h,c]*a_src[h,c]  (warp/node)
__global__ void k_logits1(const float* __restrict__ a_src, const float* __restrict__ a_dst, int N) {
    int w = (blockIdx.x * blockDim.x + threadIdx.x) >> 5;
    int lane = threadIdx.x & 31;
    if (w >= N) return;
    #pragma unroll
    for (int h = 0; h < 4; ++h) {
        float v = g_xp1[(size_t)w * 128 + h * 32 + lane];
        float s = v * a_src[h * 32 + lane];
        float d = v * a_dst[h * 32 + lane];
        #pragma unroll
        for (int o = 16; o; o >>= 1) {
            s += __shfl_xor_sync(0xffffffffu, s, o);
            d += __shfl_xor_sync(0xffffffffu, d, o);
        }
        if (lane == 0) { g_als1[w * 4 + h] = s; g_ald1[w * 4 + h] = d; }
    }
}

// layer-1 segment softmax + aggregation. One warp per destination node.
__global__ void k_agg1(const float* __restrict__ b1, int N) {
    int w = (blockIdx.x * blockDim.x + threadIdx.x) >> 5;
    int lane = threadIdx.x & 31;
    if (w >= N) return;
    int beg = g_off[w], end = g_off[w + 1];
    float ald0 = g_ald1[w * 4 + 0], ald1v = g_ald1[w * 4 + 1];
    float ald2 = g_ald1[w * 4 + 2], ald3 = g_ald1[w * 4 + 3];
    float den0 = 0.f, den1 = 0.f, den2 = 0.f, den3 = 0.f;
    // pass 1: lane-parallel exp numerators + denominator
    for (int e = beg + lane; e < end; e += 32) {
        int s = g_srcs[e];
        float4 al = *(const float4*)(g_als1 + (size_t)s * 4);
        float t0 = al.x + ald0;  t0 = t0 > 0.f ? t0 : 0.2f * t0;
        float t1 = al.y + ald1v; t1 = t1 > 0.f ? t1 : 0.2f * t1;
        float t2 = al.z + ald2;  t2 = t2 > 0.f ? t2 : 0.2f * t2;
        float t3 = al.w + ald3;  t3 = t3 > 0.f ? t3 : 0.2f * t3;
        float4 ex;
        ex.x = __expf(t0); ex.y = __expf(t1); ex.z = __expf(t2); ex.w = __expf(t3);
        *(float4*)(g_ex + (size_t)e * 4) = ex;
        den0 += ex.x; den1 += ex.y; den2 += ex.z; den3 += ex.w;
    }
    __syncwarp();
    #pragma unroll
    for (int o = 16; o; o >>= 1) {
        den0 += __shfl_xor_sync(0xffffffffu, den0, o);
        den1 += __shfl_xor_sync(0xffffffffu, den1, o);
        den2 += __shfl_xor_sync(0xffffffffu, den2, o);
        den3 += __shfl_xor_sync(0xffffffffu, den3, o);
    }
    float inv0 = 1.f / (den0 + 1e-16f), inv1 = 1.f / (den1 + 1e-16f);
    float inv2 = 1.f / (den2 + 1e-16f), inv3 = 1.f / (den3 + 1e-16f);
    // pass 2: coalesced gather-accumulate (lane = channel c)
    float a0 = 0.f, a1 = 0.f, a2 = 0.f, a3 = 0.f;
    for (int e = beg; e < end; ++e) {
        int s = g_srcs[e];                                  // broadcast
        float4 ex = *(const float4*)(g_ex + (size_t)e * 4); // broadcast
        const float* xr = g_xp1 + (size_t)s * 128;
        a0 += xr[lane]      * (ex.x * inv0);
        a1 += xr[32 + lane] * (ex.y * inv1);
        a2 += xr[64 + lane] * (ex.z * inv2);
        a3 += xr[96 + lane] * (ex.w * inv3);
    }
    float v;
    v = a0 + b1[lane];      g_h1[(size_t)w * 128 + lane]      = v > 0.f ? v : (__expf(v) - 1.f);
    v = a1 + b1[32 + lane]; g_h1[(size_t)w * 128 + 32 + lane] = v > 0.f ? v : (__expf(v) - 1.f);
    v = a2 + b1[64 + lane]; g_h1[(size_t)w * 128 + 64 + lane] = v > 0.f ? v : (__expf(v) - 1.f);
    v = a3 + b1[96 + lane]; g_h1[(size_t)w * 128 + 96 + lane] = v > 0.f ? v : (__expf(v) - 1.f);
}

// layer 2 projection xp2 = h1 @ W2 (128->32), fused logits. 8 nodes/block, warp/node.
__global__ void k_gemm2(const float* __restrict__ W2, const float* __restrict__ a_src2,
                        const float* __restrict__ a_dst2, int N) {
    __shared__ float ws[128 * 32];
    __shared__ float hs[8][128];
    int tid = threadIdx.x, lane = tid & 31, w = tid >> 5;
    int n = blockIdx.x * 8 + w;
    for (int i = tid; i < 4096; i += 256) ws[i] = W2[i];
    if (n < N)
        for (int k = lane; k < 128; k += 32) hs[w][k] = g_h1[(size_t)n * 128 + k];
    __syncthreads();
    if (n >= N) return;
    float acc = 0.f;
    #pragma unroll
    for (int k4 = 0; k4 < 32; ++k4) {
        float4 h4 = *(const float4*)&hs[w][k4 * 4];
        acc += h4.x * ws[(k4 * 4 + 0) * 32 + lane];
        acc += h4.y * ws[(k4 * 4 + 1) * 32 + lane];
        acc += h4.z * ws[(k4 * 4 + 2) * 32 + lane];
        acc += h4.w * ws[(k4 * 4 + 3) * 32 + lane];
    }
    g_xp2[(size_t)n * 32 + lane] = acc;
    float s = acc * a_src2[lane];
    float d = acc * a_dst2[lane];
    #pragma unroll
    for (int o = 16; o; o >>= 1) {
        s += __shfl_xor_sync(0xffffffffu, s, o);
        d += __shfl_xor_sync(0xffffffffu, d, o);
    }
    if (lane == 0) { g_als2[n] = s; g_ald2[n] = d; }
}

// layer-2 aggregation (H=1, C=32), warp per node, writes final output.
__global__ void k_agg2(const float* __restrict__ b2, float* __restrict__ out, int N) {
    int w = (blockIdx.x * blockDim.x + threadIdx.x) >> 5;
    int lane = threadIdx.x & 31;
    if (w >= N) return;
    int beg = g_off[w], end = g_off[w + 1];
    float ald = g_ald2[w];
    float den = 0.f;
    for (int e = beg + lane; e < end; e += 32) {
        int s = g_srcs[e];
        float t = g_als2[s] + ald;
        t = t > 0.f ? t : 0.2f * t;
        float ex = __expf(t);
        g_ex[e] = ex;
        den += ex;
    }
    __syncwarp();
    #pragma unroll
    for (int o = 16; o; o >>= 1) den += __shfl_xor_sync(0xffffffffu, den, o);
    float inv = 1.f / (den + 1e-16f);
    float acc = 0.f;
    for (int e = beg; e < end; ++e) {
        int s = g_srcs[e];
        acc += g_xp2[(size_t)s * 32 + lane] * (g_ex[e] * inv);
    }
    out[(size_t)w * 32 + lane] = acc + b2[lane];
}

extern "C" void kernel_launch(void* const* d_in, const int* in_sizes, int n_in,
                              void* d_out, int out_size) {
    const float* x      = (const float*)d_in[0];
    const void*  ei     = d_in[1];                 // int32 or int64, detected on device
    const float* W1     = (const float*)d_in[2];
    const float* a_src1 = (const float*)d_in[3];
    const float* a_dst1 = (const float*)d_in[4];
    const float* b1     = (const float*)d_in[5];
    const float* W2     = (const float*)d_in[6];
    const float* a_src2 = (const float*)d_in[7];
    const float* a_dst2 = (const float*)d_in[8];
    const float* b2     = (const float*)d_in[9];
    float* out = (float*)d_out;

    int N = in_sizes[0] / 128;  // 50000
    int E = in_sizes[1] / 2;    // 1600000
    int NB = (N + 255) / 256;   // 196

    // one-time side stream + fork/join events (host-side resources only)
    static cudaStream_t s2 = nullptr;
    static cudaEvent_t ev_fork = nullptr, ev_join = nullptr;
    if (!s2) {
        cudaStreamCreateWithFlags(&s2, cudaStreamNonBlocking);
        cudaEventCreateWithFlags(&ev_fork, cudaEventDisableTiming);
        cudaEventCreateWithFlags(&ev_join, cudaEventDisableTiming);
    }

    // ---- fork: GEMM1 + logits on side stream, CSR build on main stream ----
    cudaEventRecord(ev_fork, 0);
    cudaStreamWaitEvent(s2, ev_fork, 0);

    k_gemm1  <<<(N + 31) / 32, 256, 0, s2>>>(x, W1, N);
    k_logits1<<<(N + 7) / 8, 256, 0, s2>>>(a_src1, a_dst1, N);
    cudaEventRecord(ev_join, s2);

    // CSR build (per launch — no caching allowed)
    k_detect  <<<1, 256>>>((const int*)ei);
    k_zero_deg<<<(N + 255) / 256, 256>>>(N);
    k_count   <<<2048, 256>>>(ei, N, E);
    k_scan1   <<<NB, 256>>>(N);
    k_scan2   <<<1, 256>>>(NB, N);
    k_scan3   <<<NB, 256>>>(N);
    k_scatter <<<2048, 256>>>(ei, N, E);

    // ---- join: agg1 needs both CSR and xp1/logits ----
    cudaStreamWaitEvent(0, ev_join, 0);

    // layer 1 aggregation
    k_agg1<<<(N + 7) / 8, 256>>>(b1, N);

    // layer 2
    k_gemm2<<<(N + 7) / 8, 256>>>(W2, a_src2, a_dst2, N);
    k_agg2 <<<(N + 7) / 8, 256>>>(b2, out, N);
}